// round 7
// baseline (speedup 1.0000x reference)
#include <cuda_runtime.h>
#include <math_constants.h>

#define NB 16
#define NQ 16
#define ND 1024
#define NH 16
#define NDH 64
#define NC 4096
#define NL 4112
#define NSPLIT 8

#define KUP_OFF (NB*NQ*ND)                        /* 262144 */
#define VUP_OFF (KUP_OFF + NB*NH*NL*NDH)          /* 262144 + 67371008 */

// scratch (allocation-free: device globals)
__device__ float g_q[NB*NQ*ND];                       // projected Q
__device__ float g_x[NB*NQ*ND];                       // attention output
__device__ float g_part[(size_t)NB*NH*NSPLIT*NQ*NDH]; // split partial acc (8 MB)
__device__ float g_m[NB*NH*NSPLIT*NQ];                // split row max
__device__ float g_l[NB*NH*NSPLIT*NQ];                // split row sum

// ---------------------------------------------------------------------------
// GEMM body: 64x64 tile, BK=16, 4x4 microtile, double-buffered smem,
// register prefetch of next global tile. 256 threads.
// ---------------------------------------------------------------------------
struct SmemGemm {
    float As[2][16][68];
    float Bs[2][16][68];
};

__device__ __forceinline__ void gemm_compute(
    const float* __restrict__ X, const float* __restrict__ W,
    SmemGemm& sm, int bm, int bn, int t, float acc[4][4])
{
    const int arow = t >> 2;            // 0..63
    const int acol = (t & 3) << 2;      // 0,4,8,12
    const int brow = t >> 4;            // 0..15
    const int bcol = (t & 15) << 2;     // 0..60
    const int tn = t & 15, tm = t >> 4;

    const float* ap = &X[(size_t)(bm + arow) * ND + acol];
    const float* bp = &W[(size_t)brow * ND + bn + bcol];

    float4 av = *(const float4*)ap;
    float4 bv = *(const float4*)bp;

    int buf = 0;
    for (int k0 = 0; k0 < ND; k0 += 16) {
        sm.As[buf][acol + 0][arow] = av.x;
        sm.As[buf][acol + 1][arow] = av.y;
        sm.As[buf][acol + 2][arow] = av.z;
        sm.As[buf][acol + 3][arow] = av.w;
        *(float4*)&sm.Bs[buf][brow][bcol] = bv;
        __syncthreads();
        if (k0 + 16 < ND) {
            av = *(const float4*)(ap + k0 + 16);
            bv = *(const float4*)(bp + (size_t)(k0 + 16) * ND);
        }
#pragma unroll
        for (int kk = 0; kk < 16; kk++) {
            float4 a = *(float4*)&sm.As[buf][kk][tm << 2];
            float4 b = *(float4*)&sm.Bs[buf][kk][tn << 2];
            acc[0][0] += a.x * b.x; acc[0][1] += a.x * b.y; acc[0][2] += a.x * b.z; acc[0][3] += a.x * b.w;
            acc[1][0] += a.y * b.x; acc[1][1] += a.y * b.y; acc[1][2] += a.y * b.z; acc[1][3] += a.y * b.w;
            acc[2][0] += a.z * b.x; acc[2][1] += a.z * b.y; acc[2][2] += a.z * b.z; acc[2][3] += a.z * b.w;
            acc[3][0] += a.w * b.x; acc[3][1] += a.w * b.y; acc[3][2] += a.w * b.z; acc[3][3] += a.w * b.w;
        }
        buf ^= 1;
    }
}

// Fused Q/K/V projections: blockIdx.z selects which projection.
__global__ __launch_bounds__(256) void gemm_qkv(
    const float* __restrict__ Xq, const float* __restrict__ Xk, const float* __restrict__ Xv,
    const float* __restrict__ Wq, const float* __restrict__ Wk, const float* __restrict__ Wv,
    const float* __restrict__ bq, const float* __restrict__ bk, const float* __restrict__ bv,
    float* __restrict__ out)
{
    __shared__ SmemGemm sm;
    const int mode = blockIdx.z;
    const float* X    = (mode == 0) ? Xq : (mode == 1) ? Xk : Xv;
    const float* W    = (mode == 0) ? Wq : (mode == 1) ? Wk : Wv;
    const float* bias = (mode == 0) ? bq : (mode == 1) ? bk : bv;

    const int bn = blockIdx.x * 64;
    const int bm = blockIdx.y * 64;
    const int t  = threadIdx.x;
    const int tn = t & 15, tm = t >> 4;

    float acc[4][4] = {};
    gemm_compute(X, W, sm, bm, bn, t, acc);

#pragma unroll
    for (int i = 0; i < 4; i++) {
        const int row = bm + (tm << 2) + i;
#pragma unroll
        for (int j = 0; j < 4; j++) {
            const int col = bn + (tn << 2) + j;
            const float v = acc[i][j] + bias[col];
            if (mode == 0) {
                g_q[(size_t)row * ND + col] = v;
            } else {
                // split heads: row=(b,qi), col=(h,d) -> [b,h,C+qi,d]
                const int b = row >> 4, qi = row & 15;
                const int h = col >> 6, d = col & 63;
                const size_t off = (mode == 1) ? (size_t)KUP_OFF : (size_t)VUP_OFF;
                out[off + (((size_t)(b * NH + h) * NL) + NC + qi) * NDH + d] = v;
            }
        }
    }
}

// Output projection: g_x @ Wo + bo -> out[0..]
__global__ __launch_bounds__(256) void gemm_o(
    const float* __restrict__ Wo, const float* __restrict__ bo,
    float* __restrict__ out)
{
    __shared__ SmemGemm sm;
    const int bn = blockIdx.x * 64;
    const int bm = blockIdx.y * 64;
    const int t  = threadIdx.x;
    const int tn = t & 15, tm = t >> 4;

    float acc[4][4] = {};
    gemm_compute((const float*)g_x, Wo, sm, bm, bn, t, acc);

#pragma unroll
    for (int i = 0; i < 4; i++) {
        const int row = bm + (tm << 2) + i;
#pragma unroll
        for (int j = 0; j < 4; j++) {
            const int col = bn + (tn << 2) + j;
            out[(size_t)row * ND + col] = acc[i][j] + bo[col];
        }
    }
}

// ---------------------------------------------------------------------------
// Split-KV fused attention + cache copy-out. Block = (bh, split).
// Each split flash-attends over ~512 keys, copies its cache slice to
// k_up/v_up, and writes unnormalized partials (acc, m, l) to scratch.
// ---------------------------------------------------------------------------
__global__ __launch_bounds__(256) void attn_split(
    const float* __restrict__ cache_k, const float* __restrict__ cache_v,
    const int* __restrict__ mask, float* __restrict__ out)
{
    __shared__ float qT[64][16];    // qT[kd][r]
    __shared__ float kT[64][66];    // kT[kd][j]
    __shared__ float vsm[64][68];   // vs[j][d]  (reused as reduce buffer at end)
    __shared__ float pT[64][20];    // pT[j][r]  raw scores then probs
    __shared__ float sm_scale[16];
    __shared__ float sm_l[16];
    __shared__ float sm_m[16];

    const int t     = threadIdx.x;
    const int bh    = blockIdx.x;
    const int split = blockIdx.y;
    const int b     = bh >> 4;
    const int h     = bh & 15;

    const int k_lo = split * 512;
    const int k_hi = (split == NSPLIT - 1) ? NL : k_lo + 512;

    const float* kc = cache_k + (size_t)bh * NC * NDH;
    const float* vc = cache_v + (size_t)bh * NC * NDH;
    float* kout = out + KUP_OFF + (size_t)bh * NL * NDH;
    float* vout = out + VUP_OFF + (size_t)bh * NL * NDH;
    const int* mrow = mask + (size_t)b * NQ * NL;

    // load q tile (transposed)
    for (int idx = t; idx < NQ * NDH; idx += 256) {
        const int r = idx >> 6, kd = idx & 63;
        qT[kd][r] = g_q[(size_t)(b * NQ + r) * ND + h * NDH + kd];
    }

    // score thread map: 2 kd-groups of 128 threads, tile = 4 rows x 2 keys
    const int g2   = t >> 7;
    const int pos2 = t & 127;
    const int r0s  = (pos2 & 3) << 2;
    const int j0s  = (pos2 >> 2) << 1;
    const int kd0  = g2 << 5;

    // PV thread map: 4 j-groups of 64 threads, tile = 4 rows x 4 dims
    const int g4   = t >> 6;
    const int pos4 = t & 63;
    const int r0v  = (pos4 & 3) << 2;
    const int d0v  = (pos4 >> 2) << 2;
    const int jb   = g4 << 4;

    const int warp = t >> 5;
    const int lane = t & 31;

    float acc[4][4] = {};
    float mo[2] = {-CUDART_INF_F, -CUDART_INF_F};
    float lo[2] = {0.f, 0.f};

    for (int j0g = k_lo; j0g < k_hi; j0g += 64) {
        const int n = min(64, k_hi - j0g);
        __syncthreads();  // protect smem reuse vs previous chunk's PV reads

        // ---- load K/V chunk; copy cache rows out; tail rows read from out
        for (int idx = t; idx < (n << 4); idx += 256) {
            const int row = idx >> 4;
            const int c4  = (idx & 15) << 2;
            const int j   = j0g + row;
            float4 kv, vv;
            if (j < NC) {
                kv = *(const float4*)&kc[(size_t)j * NDH + c4];
                vv = *(const float4*)&vc[(size_t)j * NDH + c4];
                *(float4*)&kout[(size_t)j * NDH + c4] = kv;
                *(float4*)&vout[(size_t)j * NDH + c4] = vv;
            } else {
                kv = *(const float4*)&kout[(size_t)j * NDH + c4];
                vv = *(const float4*)&vout[(size_t)j * NDH + c4];
            }
            kT[c4 + 0][row] = kv.x;
            kT[c4 + 1][row] = kv.y;
            kT[c4 + 2][row] = kv.z;
            kT[c4 + 3][row] = kv.w;
            *(float4*)&vsm[row][c4] = vv;
        }
        __syncthreads();

        // ---- scores: s[16][64] = q @ K^T (kd-split over 2 groups)
        float s[4][2] = {};
#pragma unroll
        for (int kk = 0; kk < 32; kk++) {
            const int kd = kd0 + kk;
            const float4 qv = *(float4*)&qT[kd][r0s];
            const float k0v = kT[kd][j0s];
            const float k1v = kT[kd][j0s + 1];
            s[0][0] += qv.x * k0v; s[0][1] += qv.x * k1v;
            s[1][0] += qv.y * k0v; s[1][1] += qv.y * k1v;
            s[2][0] += qv.z * k0v; s[2][1] += qv.z * k1v;
            s[3][0] += qv.w * k0v; s[3][1] += qv.w * k1v;
        }
        if (g2 == 0) {
#pragma unroll
            for (int i = 0; i < 4; i++) {
                pT[j0s][r0s + i]     = s[i][0];
                pT[j0s + 1][r0s + i] = s[i][1];
            }
        }
        __syncthreads();
        if (g2 == 1) {
#pragma unroll
            for (int i = 0; i < 4; i++) {
                pT[j0s][r0s + i]     += s[i][0];
                pT[j0s + 1][r0s + i] += s[i][1];
            }
        }
        __syncthreads();

        // ---- online softmax: warp w owns rows 2w, 2w+1
#pragma unroll
        for (int rr = 0; rr < 2; rr++) {
            const int r = warp * 2 + rr;
            const int j1 = lane, j2 = lane + 32;
            float s1 = -CUDART_INF_F, s2 = -CUDART_INF_F;
            if (j1 < n) {
                s1 = pT[j1][r] * 0.125f;
                if (mrow[(size_t)r * NL + j0g + j1] == 0) s1 = -1e9f;
            }
            if (j2 < n) {
                s2 = pT[j2][r] * 0.125f;
                if (mrow[(size_t)r * NL + j0g + j2] == 0) s2 = -1e9f;
            }
            float mx = fmaxf(s1, s2);
#pragma unroll
            for (int o = 16; o; o >>= 1)
                mx = fmaxf(mx, __shfl_xor_sync(0xffffffffu, mx, o));
            const float mn = fmaxf(mo[rr], mx);
            const float scale = __expf(mo[rr] - mn);
            const float p1 = (j1 < n) ? __expf(s1 - mn) : 0.f;
            const float p2 = (j2 < n) ? __expf(s2 - mn) : 0.f;
            pT[j1][r] = p1;
            pT[j2][r] = p2;
            float ls = p1 + p2;
#pragma unroll
            for (int o = 16; o; o >>= 1)
                ls += __shfl_xor_sync(0xffffffffu, ls, o);
            lo[rr] = lo[rr] * scale + ls;
            mo[rr] = mn;
            if (lane == 0) { sm_scale[r] = scale; sm_l[r] = lo[rr]; sm_m[r] = mn; }
        }
        __syncthreads();

        // ---- PV: rescale accumulators, accumulate this group's 16 keys
#pragma unroll
        for (int i = 0; i < 4; i++) {
            const float sc = sm_scale[r0v + i];
            acc[i][0] *= sc; acc[i][1] *= sc; acc[i][2] *= sc; acc[i][3] *= sc;
        }
#pragma unroll
        for (int jj = 0; jj < 16; jj++) {
            const int j = jb + jj;
            const float4 pv = *(float4*)&pT[j][r0v];
            const float4 vv = *(float4*)&vsm[j][d0v];
            acc[0][0] += pv.x * vv.x; acc[0][1] += pv.x * vv.y; acc[0][2] += pv.x * vv.z; acc[0][3] += pv.x * vv.w;
            acc[1][0] += pv.y * vv.x; acc[1][1] += pv.y * vv.y; acc[1][2] += pv.y * vv.z; acc[1][3] += pv.y * vv.w;
            acc[2][0] += pv.z * vv.x; acc[2][1] += pv.z * vv.y; acc[2][2] += pv.z * vv.z; acc[2][3] += pv.z * vv.w;
            acc[3][0] += pv.w * vv.x; acc[3][1] += pv.w * vv.y; acc[3][2] += pv.w * vv.z; acc[3][3] += pv.w * vv.w;
        }
    }

    // ---- cross-group reduction of PV partials, write unnormalized partials
    __syncthreads();
    float* red = &vsm[0][0];   // 4352 floats available; need 3072
    if (g4 > 0) {
        const int base = (g4 - 1) * 1024 + pos4 * 16;
#pragma unroll
        for (int i = 0; i < 4; i++)
#pragma unroll
            for (int k = 0; k < 4; k++)
                red[base + i * 4 + k] = acc[i][k];
    }
    __syncthreads();

    const size_t sbase = (size_t)(bh * NSPLIT + split) * NQ;
    if (g4 == 0) {
        float* pp = g_part + sbase * NDH;
#pragma unroll
        for (int i = 0; i < 4; i++) {
            const int r = r0v + i;
#pragma unroll
            for (int k = 0; k < 4; k++) {
                const float v = acc[i][k]
                    + red[pos4 * 16 + i * 4 + k]
                    + red[1024 + pos4 * 16 + i * 4 + k]
                    + red[2048 + pos4 * 16 + i * 4 + k];
                pp[(size_t)r * NDH + d0v + k] = v;
            }
        }
    }
    if (t < NQ) {
        g_m[sbase + t] = sm_m[t];
        g_l[sbase + t] = sm_l[t];
    }
}

// ---------------------------------------------------------------------------
// Combine split partials: softmax-rescale across splits, normalize, -> g_x
// ---------------------------------------------------------------------------
__global__ __launch_bounds__(256) void attn_combine()
{
    const int bh  = blockIdx.x;
    const int t   = threadIdx.x;
    const int row = t >> 4;
    const int d0  = (t & 15) << 2;
    const int b   = bh >> 4, h = bh & 15;

    float ms[NSPLIT];
    float M = -CUDART_INF_F;
#pragma unroll
    for (int s = 0; s < NSPLIT; s++) {
        ms[s] = g_m[(size_t)(bh * NSPLIT + s) * NQ + row];
        M = fmaxf(M, ms[s]);
    }
    float L = 0.f;
    float w[NSPLIT];
#pragma unroll
    for (int s = 0; s < NSPLIT; s++) {
        w[s] = __expf(ms[s] - M);
        L += g_l[(size_t)(bh * NSPLIT + s) * NQ + row] * w[s];
    }
    float4 o = {0.f, 0.f, 0.f, 0.f};
#pragma unroll
    for (int s = 0; s < NSPLIT; s++) {
        const float4 p = *(const float4*)
            &g_part[((size_t)(bh * NSPLIT + s) * NQ + row) * NDH + d0];
        o.x += w[s] * p.x; o.y += w[s] * p.y;
        o.z += w[s] * p.z; o.w += w[s] * p.w;
    }
    const float inv = 1.f / L;
    float4 r = {o.x * inv, o.y * inv, o.z * inv, o.w * inv};
    *(float4*)&g_x[(size_t)(b * NQ + row) * ND + h * NDH + d0] = r;
}

// ---------------------------------------------------------------------------
extern "C" void kernel_launch(void* const* d_in, const int* in_sizes, int n_in,
                              void* d_out, int out_size)
{
    (void)in_sizes; (void)n_in; (void)out_size;
    const float* query   = (const float*)d_in[0];
    const float* key     = (const float*)d_in[1];
    const float* value   = (const float*)d_in[2];
    const int*   mask    = (const int*)d_in[3];
    const float* cache_k = (const float*)d_in[4];
    const float* cache_v = (const float*)d_in[5];
    const float* Wq = (const float*)d_in[6];
    const float* bq = (const float*)d_in[7];
    const float* Wk = (const float*)d_in[8];
    const float* bk = (const float*)d_in[9];
    const float* Wv = (const float*)d_in[10];
    const float* bv = (const float*)d_in[11];
    const float* Wo = (const float*)d_in[12];
    const float* bo = (const float*)d_in[13];
    float* out = (float*)d_out;

    dim3 gqkv(16, 4, 3);
    gemm_qkv<<<gqkv, 256>>>(query, key, value, Wq, Wk, Wv, bq, bk, bv, out);

    dim3 ga(NB * NH, NSPLIT);
    attn_split<<<ga, 256>>>(cache_k, cache_v, mask, out);
    attn_combine<<<NB * NH, 256>>>();

    dim3 go(16, 4);
    gemm_o<<<go, 256>>>(Wo, bo, out);
}

// round 8
// speedup vs baseline: 1.0156x; 1.0156x over previous
#include <cuda_runtime.h>
#include <math_constants.h>

#define NB 16
#define NQ 16
#define ND 1024
#define NH 16
#define NDH 64
#define NC 4096
#define NL 4112
#define NSPLIT 8

#define KUP_OFF (NB*NQ*ND)                        /* 262144 */
#define VUP_OFF (KUP_OFF + NB*NH*NL*NDH)          /* 262144 + 67371008 */

// scratch (allocation-free: device globals)
__device__ float g_q[NB*NQ*ND];                       // projected Q
__device__ float g_x[NB*NQ*ND];                       // attention output
__device__ float g_part[(size_t)NB*NH*NSPLIT*NQ*NDH]; // split partial acc (8 MB)
__device__ float g_m[NB*NH*NSPLIT*NQ];                // split row max
__device__ float g_l[NB*NH*NSPLIT*NQ];                // split row sum

// ---------------------------------------------------------------------------
// GEMM body: 64x64 tile, BK=16, 4x4 microtile, double-buffered smem,
// register prefetch of next global tile. 256 threads.
// ---------------------------------------------------------------------------
struct SmemGemm {
    float As[2][16][68];
    float Bs[2][16][68];
};

__device__ __forceinline__ void gemm_compute(
    const float* __restrict__ X, const float* __restrict__ W,
    SmemGemm& sm, int bm, int bn, int t, float acc[4][4])
{
    const int arow = t >> 2;            // 0..63
    const int acol = (t & 3) << 2;      // 0,4,8,12
    const int brow = t >> 4;            // 0..15
    const int bcol = (t & 15) << 2;     // 0..60
    const int tn = t & 15, tm = t >> 4;

    const float* ap = &X[(size_t)(bm + arow) * ND + acol];
    const float* bp = &W[(size_t)brow * ND + bn + bcol];

    float4 av = *(const float4*)ap;
    float4 bv = *(const float4*)bp;

    int buf = 0;
    for (int k0 = 0; k0 < ND; k0 += 16) {
        sm.As[buf][acol + 0][arow] = av.x;
        sm.As[buf][acol + 1][arow] = av.y;
        sm.As[buf][acol + 2][arow] = av.z;
        sm.As[buf][acol + 3][arow] = av.w;
        *(float4*)&sm.Bs[buf][brow][bcol] = bv;
        __syncthreads();
        if (k0 + 16 < ND) {
            av = *(const float4*)(ap + k0 + 16);
            bv = *(const float4*)(bp + (size_t)(k0 + 16) * ND);
        }
#pragma unroll
        for (int kk = 0; kk < 16; kk++) {
            float4 a = *(float4*)&sm.As[buf][kk][tm << 2];
            float4 b = *(float4*)&sm.Bs[buf][kk][tn << 2];
            acc[0][0] += a.x * b.x; acc[0][1] += a.x * b.y; acc[0][2] += a.x * b.z; acc[0][3] += a.x * b.w;
            acc[1][0] += a.y * b.x; acc[1][1] += a.y * b.y; acc[1][2] += a.y * b.z; acc[1][3] += a.y * b.w;
            acc[2][0] += a.z * b.x; acc[2][1] += a.z * b.y; acc[2][2] += a.z * b.z; acc[2][3] += a.z * b.w;
            acc[3][0] += a.w * b.x; acc[3][1] += a.w * b.y; acc[3][2] += a.w * b.z; acc[3][3] += a.w * b.w;
        }
        buf ^= 1;
    }
}

// Fused Q/K/V projections: blockIdx.z selects which projection.
__global__ __launch_bounds__(256) void gemm_qkv(
    const float* __restrict__ Xq, const float* __restrict__ Xk, const float* __restrict__ Xv,
    const float* __restrict__ Wq, const float* __restrict__ Wk, const float* __restrict__ Wv,
    const float* __restrict__ bq, const float* __restrict__ bk, const float* __restrict__ bv,
    float* __restrict__ out)
{
    __shared__ SmemGemm sm;
    const int mode = blockIdx.z;
    const float* X    = (mode == 0) ? Xq : (mode == 1) ? Xk : Xv;
    const float* W    = (mode == 0) ? Wq : (mode == 1) ? Wk : Wv;
    const float* bias = (mode == 0) ? bq : (mode == 1) ? bk : bv;

    const int bn = blockIdx.x * 64;
    const int bm = blockIdx.y * 64;
    const int t  = threadIdx.x;
    const int tn = t & 15, tm = t >> 4;

    float acc[4][4] = {};
    gemm_compute(X, W, sm, bm, bn, t, acc);

#pragma unroll
    for (int i = 0; i < 4; i++) {
        const int row = bm + (tm << 2) + i;
#pragma unroll
        for (int j = 0; j < 4; j++) {
            const int col = bn + (tn << 2) + j;
            const float v = acc[i][j] + bias[col];
            if (mode == 0) {
                g_q[(size_t)row * ND + col] = v;
            } else {
                // split heads: row=(b,qi), col=(h,d) -> [b,h,C+qi,d]
                const int b = row >> 4, qi = row & 15;
                const int h = col >> 6, d = col & 63;
                const size_t off = (mode == 1) ? (size_t)KUP_OFF : (size_t)VUP_OFF;
                out[off + (((size_t)(b * NH + h) * NL) + NC + qi) * NDH + d] = v;
            }
        }
    }
}

// Output projection: g_x @ Wo + bo -> out[0..]
__global__ __launch_bounds__(256) void gemm_o(
    const float* __restrict__ Wo, const float* __restrict__ bo,
    float* __restrict__ out)
{
    __shared__ SmemGemm sm;
    const int bn = blockIdx.x * 64;
    const int bm = blockIdx.y * 64;
    const int t  = threadIdx.x;
    const int tn = t & 15, tm = t >> 4;

    float acc[4][4] = {};
    gemm_compute((const float*)g_x, Wo, sm, bm, bn, t, acc);

#pragma unroll
    for (int i = 0; i < 4; i++) {
        const int row = bm + (tm << 2) + i;
#pragma unroll
        for (int j = 0; j < 4; j++) {
            const int col = bn + (tn << 2) + j;
            out[(size_t)row * ND + col] = acc[i][j] + bo[col];
        }
    }
}

// ---------------------------------------------------------------------------
// Split-KV fused attention + cache copy-out. Block = (bh, split).
// Each split flash-attends over ~512 keys, copies its cache slice to
// k_up/v_up, and writes unnormalized partials (acc, m, l) to scratch.
// ---------------------------------------------------------------------------
__global__ __launch_bounds__(256) void attn_split(
    const float* __restrict__ cache_k, const float* __restrict__ cache_v,
    const int* __restrict__ mask, float* __restrict__ out)
{
    __shared__ float qT[64][16];    // qT[kd][r]
    __shared__ float kT[64][66];    // kT[kd][j]
    __shared__ float vsm[64][68];   // vs[j][d]  (reused as reduce buffer at end)
    __shared__ float pT[64][20];    // pT[j][r]  raw scores then probs
    __shared__ float sm_scale[16];
    __shared__ float sm_l[16];
    __shared__ float sm_m[16];

    const int t     = threadIdx.x;
    const int bh    = blockIdx.x;
    const int split = blockIdx.y;
    const int b     = bh >> 4;
    const int h     = bh & 15;

    const int k_lo = split * 512;
    const int k_hi = (split == NSPLIT - 1) ? NL : k_lo + 512;

    const float* kc = cache_k + (size_t)bh * NC * NDH;
    const float* vc = cache_v + (size_t)bh * NC * NDH;
    float* kout = out + KUP_OFF + (size_t)bh * NL * NDH;
    float* vout = out + VUP_OFF + (size_t)bh * NL * NDH;
    const int* mrow = mask + (size_t)b * NQ * NL;

    // load q tile (transposed)
    for (int idx = t; idx < NQ * NDH; idx += 256) {
        const int r = idx >> 6, kd = idx & 63;
        qT[kd][r] = g_q[(size_t)(b * NQ + r) * ND + h * NDH + kd];
    }

    // score thread map: 2 kd-groups of 128 threads, tile = 4 rows x 2 keys
    const int g2   = t >> 7;
    const int pos2 = t & 127;
    const int r0s  = (pos2 & 3) << 2;
    const int j0s  = (pos2 >> 2) << 1;
    const int kd0  = g2 << 5;

    // PV thread map: 4 j-groups of 64 threads, tile = 4 rows x 4 dims
    const int g4   = t >> 6;
    const int pos4 = t & 63;
    const int r0v  = (pos4 & 3) << 2;
    const int d0v  = (pos4 >> 2) << 2;
    const int jb   = g4 << 4;

    const int warp = t >> 5;
    const int lane = t & 31;

    float acc[4][4] = {};
    float mo[2] = {-CUDART_INF_F, -CUDART_INF_F};
    float lo[2] = {0.f, 0.f};

    for (int j0g = k_lo; j0g < k_hi; j0g += 64) {
        const int n = min(64, k_hi - j0g);
        __syncthreads();  // protect smem reuse vs previous chunk's PV reads

        // ---- load K/V chunk; copy cache rows out; tail rows read from out
        for (int idx = t; idx < (n << 4); idx += 256) {
            const int row = idx >> 4;
            const int c4  = (idx & 15) << 2;
            const int j   = j0g + row;
            float4 kv, vv;
            if (j < NC) {
                kv = *(const float4*)&kc[(size_t)j * NDH + c4];
                vv = *(const float4*)&vc[(size_t)j * NDH + c4];
                *(float4*)&kout[(size_t)j * NDH + c4] = kv;
                *(float4*)&vout[(size_t)j * NDH + c4] = vv;
            } else {
                kv = *(const float4*)&kout[(size_t)j * NDH + c4];
                vv = *(const float4*)&vout[(size_t)j * NDH + c4];
            }
            kT[c4 + 0][row] = kv.x;
            kT[c4 + 1][row] = kv.y;
            kT[c4 + 2][row] = kv.z;
            kT[c4 + 3][row] = kv.w;
            *(float4*)&vsm[row][c4] = vv;
        }
        __syncthreads();

        // ---- scores: s[16][64] = q @ K^T (kd-split over 2 groups)
        float s[4][2] = {};
#pragma unroll
        for (int kk = 0; kk < 32; kk++) {
            const int kd = kd0 + kk;
            const float4 qv = *(float4*)&qT[kd][r0s];
            const float k0v = kT[kd][j0s];
            const float k1v = kT[kd][j0s + 1];
            s[0][0] += qv.x * k0v; s[0][1] += qv.x * k1v;
            s[1][0] += qv.y * k0v; s[1][1] += qv.y * k1v;
            s[2][0] += qv.z * k0v; s[2][1] += qv.z * k1v;
            s[3][0] += qv.w * k0v; s[3][1] += qv.w * k1v;
        }
        if (g2 == 0) {
#pragma unroll
            for (int i = 0; i < 4; i++) {
                pT[j0s][r0s + i]     = s[i][0];
                pT[j0s + 1][r0s + i] = s[i][1];
            }
        }
        __syncthreads();
        if (g2 == 1) {
#pragma unroll
            for (int i = 0; i < 4; i++) {
                pT[j0s][r0s + i]     += s[i][0];
                pT[j0s + 1][r0s + i] += s[i][1];
            }
        }
        __syncthreads();

        // ---- online softmax: warp w owns rows 2w, 2w+1
#pragma unroll
        for (int rr = 0; rr < 2; rr++) {
            const int r = warp * 2 + rr;
            const int j1 = lane, j2 = lane + 32;
            float s1 = -CUDART_INF_F, s2 = -CUDART_INF_F;
            if (j1 < n) {
                s1 = pT[j1][r] * 0.125f;
                if (mrow[(size_t)r * NL + j0g + j1] == 0) s1 = -1e9f;
            }
            if (j2 < n) {
                s2 = pT[j2][r] * 0.125f;
                if (mrow[(size_t)r * NL + j0g + j2] == 0) s2 = -1e9f;
            }
            float mx = fmaxf(s1, s2);
#pragma unroll
            for (int o = 16; o; o >>= 1)
                mx = fmaxf(mx, __shfl_xor_sync(0xffffffffu, mx, o));
            const float mn = fmaxf(mo[rr], mx);
            const float scale = __expf(mo[rr] - mn);
            const float p1 = (j1 < n) ? __expf(s1 - mn) : 0.f;
            const float p2 = (j2 < n) ? __expf(s2 - mn) : 0.f;
            pT[j1][r] = p1;
            pT[j2][r] = p2;
            float ls = p1 + p2;
#pragma unroll
            for (int o = 16; o; o >>= 1)
                ls += __shfl_xor_sync(0xffffffffu, ls, o);
            lo[rr] = lo[rr] * scale + ls;
            mo[rr] = mn;
            if (lane == 0) { sm_scale[r] = scale; sm_l[r] = lo[rr]; sm_m[r] = mn; }
        }
        __syncthreads();

        // ---- PV: rescale accumulators, accumulate this group's 16 keys
#pragma unroll
        for (int i = 0; i < 4; i++) {
            const float sc = sm_scale[r0v + i];
            acc[i][0] *= sc; acc[i][1] *= sc; acc[i][2] *= sc; acc[i][3] *= sc;
        }
#pragma unroll
        for (int jj = 0; jj < 16; jj++) {
            const int j = jb + jj;
            const float4 pv = *(float4*)&pT[j][r0v];
            const float4 vv = *(float4*)&vsm[j][d0v];
            acc[0][0] += pv.x * vv.x; acc[0][1] += pv.x * vv.y; acc[0][2] += pv.x * vv.z; acc[0][3] += pv.x * vv.w;
            acc[1][0] += pv.y * vv.x; acc[1][1] += pv.y * vv.y; acc[1][2] += pv.y * vv.z; acc[1][3] += pv.y * vv.w;
            acc[2][0] += pv.z * vv.x; acc[2][1] += pv.z * vv.y; acc[2][2] += pv.z * vv.z; acc[2][3] += pv.z * vv.w;
            acc[3][0] += pv.w * vv.x; acc[3][1] += pv.w * vv.y; acc[3][2] += pv.w * vv.z; acc[3][3] += pv.w * vv.w;
        }
    }

    // ---- cross-group reduction of PV partials, write unnormalized partials
    __syncthreads();
    float* red = &vsm[0][0];   // 4352 floats available; need 3072
    if (g4 > 0) {
        const int base = (g4 - 1) * 1024 + pos4 * 16;
#pragma unroll
        for (int i = 0; i < 4; i++)
#pragma unroll
            for (int k = 0; k < 4; k++)
                red[base + i * 4 + k] = acc[i][k];
    }
    __syncthreads();

    const size_t sbase = (size_t)(bh * NSPLIT + split) * NQ;
    if (g4 == 0) {
        float* pp = g_part + sbase * NDH;
#pragma unroll
        for (int i = 0; i < 4; i++) {
            const int r = r0v + i;
#pragma unroll
            for (int k = 0; k < 4; k++) {
                const float v = acc[i][k]
                    + red[pos4 * 16 + i * 4 + k]
                    + red[1024 + pos4 * 16 + i * 4 + k]
                    + red[2048 + pos4 * 16 + i * 4 + k];
                pp[(size_t)r * NDH + d0v + k] = v;
            }
        }
    }
    if (t < NQ) {
        g_m[sbase + t] = sm_m[t];
        g_l[sbase + t] = sm_l[t];
    }
}

// ---------------------------------------------------------------------------
// Combine split partials: softmax-rescale across splits, normalize, -> g_x
// ---------------------------------------------------------------------------
__global__ __launch_bounds__(256) void attn_combine()
{
    const int bh  = blockIdx.x;
    const int t   = threadIdx.x;
    const int row = t >> 4;
    const int d0  = (t & 15) << 2;
    const int b   = bh >> 4, h = bh & 15;

    float ms[NSPLIT];
    float M = -CUDART_INF_F;
#pragma unroll
    for (int s = 0; s < NSPLIT; s++) {
        ms[s] = g_m[(size_t)(bh * NSPLIT + s) * NQ + row];
        M = fmaxf(M, ms[s]);
    }
    float L = 0.f;
    float w[NSPLIT];
#pragma unroll
    for (int s = 0; s < NSPLIT; s++) {
        w[s] = __expf(ms[s] - M);
        L += g_l[(size_t)(bh * NSPLIT + s) * NQ + row] * w[s];
    }
    float4 o = {0.f, 0.f, 0.f, 0.f};
#pragma unroll
    for (int s = 0; s < NSPLIT; s++) {
        const float4 p = *(const float4*)
            &g_part[((size_t)(bh * NSPLIT + s) * NQ + row) * NDH + d0];
        o.x += w[s] * p.x; o.y += w[s] * p.y;
        o.z += w[s] * p.z; o.w += w[s] * p.w;
    }
    const float inv = 1.f / L;
    float4 r = {o.x * inv, o.y * inv, o.z * inv, o.w * inv};
    *(float4*)&g_x[(size_t)(b * NQ + row) * ND + h * NDH + d0] = r;
}

// ---------------------------------------------------------------------------
extern "C" void kernel_launch(void* const* d_in, const int* in_sizes, int n_in,
                              void* d_out, int out_size)
{
    (void)in_sizes; (void)n_in; (void)out_size;
    const float* query   = (const float*)d_in[0];
    const float* key     = (const float*)d_in[1];
    const float* value   = (const float*)d_in[2];
    const int*   mask    = (const int*)d_in[3];
    const float* cache_k = (const float*)d_in[4];
    const float* cache_v = (const float*)d_in[5];
    const float* Wq = (const float*)d_in[6];
    const float* bq = (const float*)d_in[7];
    const float* Wk = (const float*)d_in[8];
    const float* bk = (const float*)d_in[9];
    const float* Wv = (const float*)d_in[10];
    const float* bv = (const float*)d_in[11];
    const float* Wo = (const float*)d_in[12];
    const float* bo = (const float*)d_in[13];
    float* out = (float*)d_out;

    dim3 gqkv(16, 4, 3);
    gemm_qkv<<<gqkv, 256>>>(query, key, value, Wq, Wk, Wv, bq, bk, bv, out);

    dim3 ga(NB * NH, NSPLIT);
    attn_split<<<ga, 256>>>(cache_k, cache_v, mask, out);
    attn_combine<<<NB * NH, 256>>>();

    dim3 go(16, 4);
    gemm_o<<<go, 256>>>(Wo, bo, out);
}